// round 8
// baseline (speedup 1.0000x reference)
#include <cuda_runtime.h>
#include <cuda_fp16.h>

#define Bq   512
#define Tt   365
#define Ff   16
#define Hh   256
#define G4   1024
#define NC   128     // CTAs
#define BS   4       // batch rows per CTA
#define NT   1024    // 4 k-quarters x (4 gate cols x 4 batch)

// dynamic SMEM layout (floats)
#define ZSP_OFF  0                 // 4 * 4096 floats
#define H1_OFF   (4 * BS * G4)     // 16384
#define H2_OFF   (H1_OFF + Hh * 8) // 18432
#define XS_OFF   (H2_OFF + Hh * 8) // 20480
#define SMEM_FLOATS (XS_OFF + Ff * 8)
#define SMEM_BYTES  (SMEM_FLOATS * 4)

typedef unsigned long long u64;

// ---------------------------------------------------------------------------
// fp16 weights (L2-resident), fp32 fused biases.
// g_w1: [272 rows][1024 halves]  (W_ih1 16 rows then W_hh1 256 rows)
// g_w2: [256 rows][2048 halves]  row k = 256 groups of [wa0..3, wb0..3]
// ---------------------------------------------------------------------------
__device__ __half g_w1[(Ff + Hh) * G4];
__device__ __half g_w2[Hh * 2 * G4];
__device__ float  g_b1[G4];
__device__ float  g_b2[G4];

__device__ __forceinline__ u64 fma2(u64 a, u64 b, u64 c) {
    u64 d; asm("fma.rn.f32x2 %0, %1, %2, %3;" : "=l"(d) : "l"(a), "l"(b), "l"(c)); return d;
}
__device__ __forceinline__ u64 cvt2(unsigned hw) {
    u64 r;
    asm("{\n\t"
        ".reg .b16 l, h;\n\t"
        ".reg .f32 f0, f1;\n\t"
        "mov.b32 {l, h}, %1;\n\t"
        "cvt.f32.f16 f0, l;\n\t"
        "cvt.f32.f16 f1, h;\n\t"
        "mov.b64 %0, {f0, f1};\n\t"
        "}" : "=l"(r) : "r"(hw));
    return r;
}
__device__ __forceinline__ float sigf(float x) { return 1.0f / (1.0f + __expf(-x)); }

// ---------------------------------------------------------------------------
__global__ void prep_kernel(const float* __restrict__ wih1, const float* __restrict__ whh1,
                            const float* __restrict__ bih1, const float* __restrict__ bhh1,
                            const float* __restrict__ wih2, const float* __restrict__ whh2,
                            const float* __restrict__ bih2, const float* __restrict__ bhh2) {
    int idx = blockIdx.x * blockDim.x + threadIdx.x;
    if (idx < Hh * 2 * G4) {
        int k = idx >> 11, r = idx & 2047;
        int grp = r >> 3, q = r & 7;
        float v;
        if (q < 4) { int col = grp * 4 + q;       v = wih2[col * Hh + k]; }
        else       { int col = grp * 4 + (q - 4); v = whh2[col * Hh + k]; }
        g_w2[idx] = __float2half_rn(v);
    }
    if (idx < (Ff + Hh) * G4) {
        int k = idx >> 10, col = idx & 1023;
        float v = (k < Ff) ? wih1[col * Ff + k] : whh1[col * Hh + (k - Ff)];
        g_w1[idx] = __float2half_rn(v);
    }
    if (idx < G4) {
        g_b1[idx] = bih1[idx] + bhh1[idx];
        g_b2[idx] = bih2[idx] + bhh2[idx];
    }
}

// ---------------------------------------------------------------------------
// Gate phase: thread (kq = tid>>8 in 0..3, ct = tid&255) -> gate cols
//   4ct..4ct+3, all 4 batch rows, QUARTER of the k-range; partials zsp[kq].
// Update phase: thread (u = tid&255, b = tid>>8) -> one (unit, batch) cell.
// h duplicated: hd[u][8] = {h0,h0,h1,h1,h2,h2,h3,h3}.
// ---------------------------------------------------------------------------
__global__ void __launch_bounds__(NT, 1)
lstm_kernel(const float* __restrict__ x,
            const float* __restrict__ wlin, const float* __restrict__ blin,
            float* __restrict__ out) {
    extern __shared__ __align__(16) float smem[];
    float* h1d = smem + H1_OFF;
    float* h2d = smem + H2_OFF;
    float* xs  = smem + XS_OFF;

    const int tid = threadIdx.x;
    const int ct  = tid & 255;
    const int kq  = tid >> 8;
    const int b0  = blockIdx.x * BS;

    if (tid < Hh) {
        float4 z4 = make_float4(0.f, 0.f, 0.f, 0.f);
        *(float4*)&h1d[tid * 8]     = z4;  *(float4*)&h1d[tid * 8 + 4] = z4;
        *(float4*)&h2d[tid * 8]     = z4;  *(float4*)&h2d[tid * 8 + 4] = z4;
    }
    float c1 = 0.f, c2 = 0.f;    // update-phase cell state: (u = ct, b = kq)

    u64 b1lo = 0, b1hi = 0, b2lo = 0, b2hi = 0;
    if (kq == 0) {
        b1lo = *(const u64*)&g_b1[4 * ct];  b1hi = *(const u64*)&g_b1[4 * ct + 2];
        b2lo = *(const u64*)&g_b2[4 * ct];  b2hi = *(const u64*)&g_b2[4 * ct + 2];
    }

    const __half* w1p = &g_w1[4 * ct];
    const __half* w1h = w1p + Ff * G4;            // h-rows of layer 1
    const __half* w2p = &g_w2[8 * ct];

    // layer-1 h-row range per quarter (kq0 also does the 16 x-rows): 68 each
    const int h1beg = (kq == 0) ? 0  : 52 + 68 * (kq - 1);
    const int h1end = (kq == 0) ? 52 : h1beg + 68;
    const int k2beg = kq * 64;

    float* zme = smem + ZSP_OFF + kq * (BS * G4);

    __syncthreads();

    for (int t = 0; t < Tt; ++t) {
        // ---- stage x_t duplicated ----
        if (tid < Ff * BS) {
            int b = tid >> 4, f = tid & 15;
            float v = __ldg(&x[((size_t)(b0 + b) * Tt + t) * Ff + f]);
            *(float2*)&xs[f * 8 + 2 * b] = make_float2(v, v);
        }
        __syncthreads();

        // ================= LAYER 1 gates (k quarter) =================
        {
            u64 a00 = b1lo, a01 = b1lo, a02 = b1lo, a03 = b1lo;
            u64 a10 = b1hi, a11 = b1hi, a12 = b1hi, a13 = b1hi;
            if (kq == 0) {
                #pragma unroll
                for (int k = 0; k < Ff; ++k) {
                    uint2 wv = __ldg((const uint2*)(w1p + (size_t)k * G4));
                    u64 w0 = cvt2(wv.x), w1 = cvt2(wv.y);
                    ulonglong2 hA = *(const ulonglong2*)&xs[k * 8];
                    ulonglong2 hB = *(const ulonglong2*)&xs[k * 8 + 4];
                    a00 = fma2(w0, hA.x, a00); a01 = fma2(w0, hA.y, a01);
                    a02 = fma2(w0, hB.x, a02); a03 = fma2(w0, hB.y, a03);
                    a10 = fma2(w1, hA.x, a10); a11 = fma2(w1, hA.y, a11);
                    a12 = fma2(w1, hB.x, a12); a13 = fma2(w1, hB.y, a13);
                }
            }
            #pragma unroll 4
            for (int k = h1beg; k < h1end; ++k) {
                uint2 wv = __ldg((const uint2*)(w1h + (size_t)k * G4));
                u64 w0 = cvt2(wv.x), w1 = cvt2(wv.y);
                ulonglong2 hA = *(const ulonglong2*)&h1d[k * 8];
                ulonglong2 hB = *(const ulonglong2*)&h1d[k * 8 + 4];
                a00 = fma2(w0, hA.x, a00); a01 = fma2(w0, hA.y, a01);
                a02 = fma2(w0, hB.x, a02); a03 = fma2(w0, hB.y, a03);
                a10 = fma2(w1, hA.x, a10); a11 = fma2(w1, hA.y, a11);
                a12 = fma2(w1, hB.x, a12); a13 = fma2(w1, hB.y, a13);
            }
            *(ulonglong2*)&zme[0 * G4 + 4 * ct] = make_ulonglong2(a00, a10);
            *(ulonglong2*)&zme[1 * G4 + 4 * ct] = make_ulonglong2(a01, a11);
            *(ulonglong2*)&zme[2 * G4 + 4 * ct] = make_ulonglong2(a02, a12);
            *(ulonglong2*)&zme[3 * G4 + 4 * ct] = make_ulonglong2(a03, a13);
        }
        __syncthreads();

        // ================= LAYER 1 update (u = ct, b = kq) =================
        {
            const int u = ct;
            const float* zb = smem + ZSP_OFF + kq * G4 * 0 + 0;  // base reused below
            const int bo = kq * G4 * 0;  (void)bo;
            float zi = 0.f, zf = 0.f, zg = 0.f, zo = 0.f;
            #pragma unroll
            for (int q = 0; q < 4; ++q) {
                const float* zp = smem + ZSP_OFF + q * (BS * G4) + kq * G4 + u;
                zi += zp[0];
                zf += zp[Hh];
                zg += zp[2 * Hh];
                zo += zp[3 * Hh];
            }
            (void)zb;
            c1 = sigf(zf) * c1 + sigf(zi) * tanhf(zg);
            float h = sigf(zo) * tanhf(c1);
            *(float2*)&h1d[u * 8 + 2 * kq] = make_float2(h, h);
        }
        __syncthreads();

        // ================= LAYER 2 gates (k quarter) =================
        {
            u64 a00 = b2lo, a01 = b2lo, a02 = b2lo, a03 = b2lo;
            u64 a10 = b2hi, a11 = b2hi, a12 = b2hi, a13 = b2hi;
            #pragma unroll 4
            for (int kk = 0; kk < 64; ++kk) {
                const int k = k2beg + kk;
                uint4 wv = __ldg((const uint4*)(w2p + (size_t)k * 2 * G4));
                u64 wa0 = cvt2(wv.x), wa1 = cvt2(wv.y);
                u64 wb0 = cvt2(wv.z), wb1 = cvt2(wv.w);
                ulonglong2 hA1 = *(const ulonglong2*)&h1d[k * 8];
                ulonglong2 hB1 = *(const ulonglong2*)&h1d[k * 8 + 4];
                ulonglong2 hA2 = *(const ulonglong2*)&h2d[k * 8];
                ulonglong2 hB2 = *(const ulonglong2*)&h2d[k * 8 + 4];
                a00 = fma2(wa0, hA1.x, a00); a01 = fma2(wa0, hA1.y, a01);
                a02 = fma2(wa0, hB1.x, a02); a03 = fma2(wa0, hB1.y, a03);
                a10 = fma2(wa1, hA1.x, a10); a11 = fma2(wa1, hA1.y, a11);
                a12 = fma2(wa1, hB1.x, a12); a13 = fma2(wa1, hB1.y, a13);
                a00 = fma2(wb0, hA2.x, a00); a01 = fma2(wb0, hA2.y, a01);
                a02 = fma2(wb0, hB2.x, a02); a03 = fma2(wb0, hB2.y, a03);
                a10 = fma2(wb1, hA2.x, a10); a11 = fma2(wb1, hA2.y, a11);
                a12 = fma2(wb1, hB2.x, a12); a13 = fma2(wb1, hB2.y, a13);
            }
            *(ulonglong2*)&zme[0 * G4 + 4 * ct] = make_ulonglong2(a00, a10);
            *(ulonglong2*)&zme[1 * G4 + 4 * ct] = make_ulonglong2(a01, a11);
            *(ulonglong2*)&zme[2 * G4 + 4 * ct] = make_ulonglong2(a02, a12);
            *(ulonglong2*)&zme[3 * G4 + 4 * ct] = make_ulonglong2(a03, a13);
        }
        __syncthreads();

        // ================= LAYER 2 update =================
        {
            const int u = ct;
            float zi = 0.f, zf = 0.f, zg = 0.f, zo = 0.f;
            #pragma unroll
            for (int q = 0; q < 4; ++q) {
                const float* zp = smem + ZSP_OFF + q * (BS * G4) + kq * G4 + u;
                zi += zp[0];
                zf += zp[Hh];
                zg += zp[2 * Hh];
                zo += zp[3 * Hh];
            }
            c2 = sigf(zf) * c2 + sigf(zi) * tanhf(zg);
            float h = sigf(zo) * tanhf(c2);
            *(float2*)&h2d[u * 8 + 2 * kq] = make_float2(h, h);
        }
        __syncthreads();
    }

    // ================= linear head =================
    if (tid < 32 * BS) {
        int b = tid >> 5, lane = tid & 31;
        float s = 0.f;
        #pragma unroll
        for (int k = lane; k < Hh; k += 32) s += h2d[k * 8 + 2 * b] * __ldg(&wlin[k]);
        #pragma unroll
        for (int off = 16; off; off >>= 1) s += __shfl_xor_sync(0xffffffffu, s, off);
        if (lane == 0) out[b0 + b] = s + blin[0];
    }
}

// ---------------------------------------------------------------------------
extern "C" void kernel_launch(void* const* d_in, const int* in_sizes, int n_in,
                              void* d_out, int out_size) {
    const float* x    = (const float*)d_in[0];
    const float* wih1 = (const float*)d_in[1];
    const float* whh1 = (const float*)d_in[2];
    const float* bih1 = (const float*)d_in[3];
    const float* bhh1 = (const float*)d_in[4];
    const float* wih2 = (const float*)d_in[5];
    const float* whh2 = (const float*)d_in[6];
    const float* bih2 = (const float*)d_in[7];
    const float* bhh2 = (const float*)d_in[8];
    const float* wlin = (const float*)d_in[9];
    const float* blin = (const float*)d_in[10];
    float* out = (float*)d_out;

    static int smem_set = 0;
    if (!smem_set) {
        cudaFuncSetAttribute(lstm_kernel,
                             cudaFuncAttributeMaxDynamicSharedMemorySize, SMEM_BYTES);
        smem_set = 1;
    }

    prep_kernel<<<(Hh * 2 * G4 + 255) / 256, 256>>>(wih1, whh1, bih1, bhh1,
                                                    wih2, whh2, bih2, bhh2);
    lstm_kernel<<<NC, NT, SMEM_BYTES>>>(x, wlin, blin, out);
}

// round 9
// speedup vs baseline: 1.0538x; 1.0538x over previous
#include <cuda_runtime.h>
#include <cuda_fp16.h>

#define Bq   512
#define Tt   365
#define Ff   16
#define Hh   256
#define G4   1024
#define NC   128     // CTAs
#define BS   4       // batch rows per CTA
#define NT   512     // 4 k-quarters x 128 col-threads (8 cols x 4 batch each)

// dynamic SMEM layout (floats)
#define ZSP_OFF  0                 // 4 * 4096 floats (per-quarter partials)
#define H1_OFF   (4 * BS * G4)     // 16384
#define H2_OFF   (H1_OFF + Hh * 8) // 18432
#define XS_OFF   (H2_OFF + Hh * 8) // 20480
#define SMEM_FLOATS (XS_OFF + Ff * 8)
#define SMEM_BYTES  (SMEM_FLOATS * 4)

typedef unsigned long long u64;

// ---------------------------------------------------------------------------
// fp16 weights (L2-resident), fp32 fused biases.
// g_w1: [272 rows][1024 halves]  (W_ih1 16 rows then W_hh1 256 rows)
// g_w2: [256 rows][2048 halves]  row k = 128 groups of [wa0..7, wb0..7]
// ---------------------------------------------------------------------------
__device__ __half g_w1[(Ff + Hh) * G4];
__device__ __half g_w2[Hh * 2 * G4];
__device__ float  g_b1[G4];
__device__ float  g_b2[G4];

__device__ __forceinline__ u64 fma2(u64 a, u64 b, u64 c) {
    u64 d; asm("fma.rn.f32x2 %0, %1, %2, %3;" : "=l"(d) : "l"(a), "l"(b), "l"(c)); return d;
}
__device__ __forceinline__ u64 cvt2(unsigned hw) {
    u64 r;
    asm("{\n\t"
        ".reg .b16 l, h;\n\t"
        ".reg .f32 f0, f1;\n\t"
        "mov.b32 {l, h}, %1;\n\t"
        "cvt.f32.f16 f0, l;\n\t"
        "cvt.f32.f16 f1, h;\n\t"
        "mov.b64 %0, {f0, f1};\n\t"
        "}" : "=l"(r) : "r"(hw));
    return r;
}
__device__ __forceinline__ float sigf(float x) { return 1.0f / (1.0f + __expf(-x)); }

// ---------------------------------------------------------------------------
__global__ void prep_kernel(const float* __restrict__ wih1, const float* __restrict__ whh1,
                            const float* __restrict__ bih1, const float* __restrict__ bhh1,
                            const float* __restrict__ wih2, const float* __restrict__ whh2,
                            const float* __restrict__ bih2, const float* __restrict__ bhh2) {
    int idx = blockIdx.x * blockDim.x + threadIdx.x;
    if (idx < Hh * 2 * G4) {
        int k = idx >> 11, r = idx & 2047;
        int grp = r >> 4, q = r & 15;           // 128 groups of 16 halves
        int col = grp * 8 + (q & 7);
        float v = (q < 8) ? wih2[col * Hh + k] : whh2[col * Hh + k];
        g_w2[idx] = __float2half_rn(v);
    }
    if (idx < (Ff + Hh) * G4) {
        int k = idx >> 10, col = idx & 1023;
        float v = (k < Ff) ? wih1[col * Ff + k] : whh1[col * Hh + (k - Ff)];
        g_w1[idx] = __float2half_rn(v);
    }
    if (idx < G4) {
        g_b1[idx] = bih1[idx] + bhh1[idx];
        g_b2[idx] = bih2[idx] + bhh2[idx];
    }
}

// ---------------------------------------------------------------------------
// Gate phase: thread (kq = tid>>7 in 0..3, ct = tid&127) -> gate cols
//   8ct..8ct+7, all 4 batch rows, QUARTER of the k-range; partials zsp[kq].
// Update phase: thread (u = tid&255, j = tid>>8) -> unit u, batch 2j,2j+1.
// h duplicated: hd[u][8] = {h0,h0,h1,h1,h2,h2,h3,h3}.
// ---------------------------------------------------------------------------
__global__ void __launch_bounds__(NT, 1)
lstm_kernel(const float* __restrict__ x,
            const float* __restrict__ wlin, const float* __restrict__ blin,
            float* __restrict__ out) {
    extern __shared__ __align__(16) float smem[];
    float* h1d = smem + H1_OFF;
    float* h2d = smem + H2_OFF;
    float* xs  = smem + XS_OFF;

    const int tid = threadIdx.x;
    const int ct  = tid & 127;
    const int kq  = tid >> 7;
    const int uu  = tid & 255;   // update-phase unit
    const int uj  = tid >> 8;    // update-phase batch pair (0 or 1)
    const int b0  = blockIdx.x * BS;

    if (tid < Hh) {
        float4 z4 = make_float4(0.f, 0.f, 0.f, 0.f);
        *(float4*)&h1d[tid * 8]     = z4;  *(float4*)&h1d[tid * 8 + 4] = z4;
        *(float4*)&h2d[tid * 8]     = z4;  *(float4*)&h2d[tid * 8 + 4] = z4;
    }
    float c1[2] = {0.f, 0.f};
    float c2[2] = {0.f, 0.f};

    // biases for 8 cols (only quarter 0 seeds them)
    u64 b1v[4] = {0, 0, 0, 0}, b2v[4] = {0, 0, 0, 0};
    if (kq == 0) {
        #pragma unroll
        for (int j = 0; j < 4; ++j) {
            b1v[j] = *(const u64*)&g_b1[8 * ct + 2 * j];
            b2v[j] = *(const u64*)&g_b2[8 * ct + 2 * j];
        }
    }

    const __half* w1p = &g_w1[8 * ct];
    const __half* w1h = w1p + Ff * G4;
    const __half* w2p = &g_w2[16 * ct];

    // layer-1 h-row range per quarter (kq0 also does the 16 x-rows): 68 each
    const int h1beg = (kq == 0) ? 0  : 52 + 68 * (kq - 1);
    const int h1end = (kq == 0) ? 52 : h1beg + 68;
    const int k2beg = kq * 64;

    float* zme = smem + ZSP_OFF + kq * (BS * G4);

    __syncthreads();

    for (int t = 0; t < Tt; ++t) {
        // ---- stage x_t duplicated ----
        if (tid < Ff * BS) {
            int b = tid >> 4, f = tid & 15;
            float v = __ldg(&x[((size_t)(b0 + b) * Tt + t) * Ff + f]);
            *(float2*)&xs[f * 8 + 2 * b] = make_float2(v, v);
        }
        __syncthreads();

        // ================= LAYER 1 gates (8 cols x 4 batch, k quarter) ======
        {
            u64 acc[4][4];   // [batch][col-pair]
            #pragma unroll
            for (int b = 0; b < 4; ++b)
                #pragma unroll
                for (int j = 0; j < 4; ++j) acc[b][j] = b1v[j];

            auto do16 = [&](u64 w0, u64 w1, u64 w2, u64 w3,
                            ulonglong2 hA, ulonglong2 hB) {
                acc[0][0] = fma2(w0, hA.x, acc[0][0]); acc[0][1] = fma2(w1, hA.x, acc[0][1]);
                acc[0][2] = fma2(w2, hA.x, acc[0][2]); acc[0][3] = fma2(w3, hA.x, acc[0][3]);
                acc[1][0] = fma2(w0, hA.y, acc[1][0]); acc[1][1] = fma2(w1, hA.y, acc[1][1]);
                acc[1][2] = fma2(w2, hA.y, acc[1][2]); acc[1][3] = fma2(w3, hA.y, acc[1][3]);
                acc[2][0] = fma2(w0, hB.x, acc[2][0]); acc[2][1] = fma2(w1, hB.x, acc[2][1]);
                acc[2][2] = fma2(w2, hB.x, acc[2][2]); acc[2][3] = fma2(w3, hB.x, acc[2][3]);
                acc[3][0] = fma2(w0, hB.y, acc[3][0]); acc[3][1] = fma2(w1, hB.y, acc[3][1]);
                acc[3][2] = fma2(w2, hB.y, acc[3][2]); acc[3][3] = fma2(w3, hB.y, acc[3][3]);
            };

            if (kq == 0) {
                #pragma unroll
                for (int k = 0; k < Ff; ++k) {
                    uint4 wv = __ldg((const uint4*)(w1p + (size_t)k * G4));
                    ulonglong2 hA = *(const ulonglong2*)&xs[k * 8];
                    ulonglong2 hB = *(const ulonglong2*)&xs[k * 8 + 4];
                    do16(cvt2(wv.x), cvt2(wv.y), cvt2(wv.z), cvt2(wv.w), hA, hB);
                }
            }
            #pragma unroll 4
            for (int k = h1beg; k < h1end; ++k) {
                uint4 wv = __ldg((const uint4*)(w1h + (size_t)k * G4));
                ulonglong2 hA = *(const ulonglong2*)&h1d[k * 8];
                ulonglong2 hB = *(const ulonglong2*)&h1d[k * 8 + 4];
                do16(cvt2(wv.x), cvt2(wv.y), cvt2(wv.z), cvt2(wv.w), hA, hB);
            }
            #pragma unroll
            for (int b = 0; b < 4; ++b) {
                *(ulonglong2*)&zme[b * G4 + 8 * ct]     = make_ulonglong2(acc[b][0], acc[b][1]);
                *(ulonglong2*)&zme[b * G4 + 8 * ct + 4] = make_ulonglong2(acc[b][2], acc[b][3]);
            }
        }
        __syncthreads();

        // ================= LAYER 1 update =================
        {
            float hv[2];
            #pragma unroll
            for (int j = 0; j < 2; ++j) {
                const int b = 2 * uj + j;
                float zi = 0.f, zf = 0.f, zg = 0.f, zo = 0.f;
                #pragma unroll
                for (int q = 0; q < 4; ++q) {
                    const float* zp = smem + ZSP_OFF + q * (BS * G4) + b * G4 + uu;
                    zi += zp[0]; zf += zp[Hh]; zg += zp[2 * Hh]; zo += zp[3 * Hh];
                }
                c1[j] = sigf(zf) * c1[j] + sigf(zi) * tanhf(zg);
                hv[j] = sigf(zo) * tanhf(c1[j]);
            }
            *(float4*)&h1d[uu * 8 + 4 * uj] = make_float4(hv[0], hv[0], hv[1], hv[1]);
        }
        __syncthreads();

        // ================= LAYER 2 gates (8 cols x 4 batch, k quarter) ======
        {
            u64 acc[4][4];
            #pragma unroll
            for (int b = 0; b < 4; ++b)
                #pragma unroll
                for (int j = 0; j < 4; ++j) acc[b][j] = b2v[j];

            auto do16 = [&](u64 w0, u64 w1, u64 w2, u64 w3,
                            ulonglong2 hA, ulonglong2 hB) {
                acc[0][0] = fma2(w0, hA.x, acc[0][0]); acc[0][1] = fma2(w1, hA.x, acc[0][1]);
                acc[0][2] = fma2(w2, hA.x, acc[0][2]); acc[0][3] = fma2(w3, hA.x, acc[0][3]);
                acc[1][0] = fma2(w0, hA.y, acc[1][0]); acc[1][1] = fma2(w1, hA.y, acc[1][1]);
                acc[1][2] = fma2(w2, hA.y, acc[1][2]); acc[1][3] = fma2(w3, hA.y, acc[1][3]);
                acc[2][0] = fma2(w0, hB.x, acc[2][0]); acc[2][1] = fma2(w1, hB.x, acc[2][1]);
                acc[2][2] = fma2(w2, hB.x, acc[2][2]); acc[2][3] = fma2(w3, hB.x, acc[2][3]);
                acc[3][0] = fma2(w0, hB.y, acc[3][0]); acc[3][1] = fma2(w1, hB.y, acc[3][1]);
                acc[3][2] = fma2(w2, hB.y, acc[3][2]); acc[3][3] = fma2(w3, hB.y, acc[3][3]);
            };

            #pragma unroll 2
            for (int kk = 0; kk < 64; ++kk) {
                const int k = k2beg + kk;
                const __half* base = w2p + (size_t)k * 2 * G4;
                uint4 wva = __ldg((const uint4*)(base));
                uint4 wvb = __ldg((const uint4*)(base + 8));
                ulonglong2 hA1 = *(const ulonglong2*)&h1d[k * 8];
                ulonglong2 hB1 = *(const ulonglong2*)&h1d[k * 8 + 4];
                ulonglong2 hA2 = *(const ulonglong2*)&h2d[k * 8];
                ulonglong2 hB2 = *(const ulonglong2*)&h2d[k * 8 + 4];
                do16(cvt2(wva.x), cvt2(wva.y), cvt2(wva.z), cvt2(wva.w), hA1, hB1);
                do16(cvt2(wvb.x), cvt2(wvb.y), cvt2(wvb.z), cvt2(wvb.w), hA2, hB2);
            }
            #pragma unroll
            for (int b = 0; b < 4; ++b) {
                *(ulonglong2*)&zme[b * G4 + 8 * ct]     = make_ulonglong2(acc[b][0], acc[b][1]);
                *(ulonglong2*)&zme[b * G4 + 8 * ct + 4] = make_ulonglong2(acc[b][2], acc[b][3]);
            }
        }
        __syncthreads();

        // ================= LAYER 2 update =================
        {
            float hv[2];
            #pragma unroll
            for (int j = 0; j < 2; ++j) {
                const int b = 2 * uj + j;
                float zi = 0.f, zf = 0.f, zg = 0.f, zo = 0.f;
                #pragma unroll
                for (int q = 0; q < 4; ++q) {
                    const float* zp = smem + ZSP_OFF + q * (BS * G4) + b * G4 + uu;
                    zi += zp[0]; zf += zp[Hh]; zg += zp[2 * Hh]; zo += zp[3 * Hh];
                }
                c2[j] = sigf(zf) * c2[j] + sigf(zi) * tanhf(zg);
                hv[j] = sigf(zo) * tanhf(c2[j]);
            }
            *(float4*)&h2d[uu * 8 + 4 * uj] = make_float4(hv[0], hv[0], hv[1], hv[1]);
        }
        __syncthreads();
    }

    // ================= linear head =================
    if (tid < 32 * BS) {
        int b = tid >> 5, lane = tid & 31;
        float s = 0.f;
        #pragma unroll
        for (int k = lane; k < Hh; k += 32) s += h2d[k * 8 + 2 * b] * __ldg(&wlin[k]);
        #pragma unroll
        for (int off = 16; off; off >>= 1) s += __shfl_xor_sync(0xffffffffu, s, off);
        if (lane == 0) out[b0 + b] = s + blin[0];
    }
}

// ---------------------------------------------------------------------------
extern "C" void kernel_launch(void* const* d_in, const int* in_sizes, int n_in,
                              void* d_out, int out_size) {
    const float* x    = (const float*)d_in[0];
    const float* wih1 = (const float*)d_in[1];
    const float* whh1 = (const float*)d_in[2];
    const float* bih1 = (const float*)d_in[3];
    const float* bhh1 = (const float*)d_in[4];
    const float* wih2 = (const float*)d_in[5];
    const float* whh2 = (const float*)d_in[6];
    const float* bih2 = (const float*)d_in[7];
    const float* bhh2 = (const float*)d_in[8];
    const float* wlin = (const float*)d_in[9];
    const float* blin = (const float*)d_in[10];
    float* out = (float*)d_out;

    static int smem_set = 0;
    if (!smem_set) {
        cudaFuncSetAttribute(lstm_kernel,
                             cudaFuncAttributeMaxDynamicSharedMemorySize, SMEM_BYTES);
        smem_set = 1;
    }

    prep_kernel<<<(Hh * 2 * G4 + 255) / 256, 256>>>(wih1, whh1, bih1, bhh1,
                                                    wih2, whh2, bih2, bhh2);
    lstm_kernel<<<NC, NT, SMEM_BYTES>>>(x, wlin, blin, out);
}

// round 10
// speedup vs baseline: 1.9621x; 1.8619x over previous
#include <cuda_runtime.h>
#include <cuda_fp16.h>

#define Bq   512
#define Tt   365
#define Ff   16
#define Hh   256
#define G4   1024
#define NCg  32      // CTAs (16 batch rows each)
#define MB   16      // batch rows per CTA
#define NT   512     // 16 warps; warp w owns gate cols [w*64, w*64+64)
#define K1T  17      // layer-1 k-tiles (272 = 16 x + 256 h1)
#define K2T  32      // layer-2 k-tiles (512 = 256 h1 + 256 h2)
#define HST  280     // hbuf row stride (f16): [x(16) | h1(256) | pad]
#define H2ST 520     // h12 row stride (f16): [h1(256) | h2(256) | pad]
#define ZST  1032    // zs row stride (f32)

// SMEM layout (bytes): hbuf 16*280*2=8960 | h12 16*520*2=16640 | zs 16*1032*4=66048
#define SMEM_BYTES (MB*HST*2 + MB*H2ST*2 + MB*ZST*4)

// ---------------------------------------------------------------------------
// Pre-packed fp16 B fragments for mma.m16n8k16 (.col B):
//   linear index ((kt*16 + w)*4 + p)*32 + lane  ->  uint4 = 8 f16:
//   halves 0..3 = tile 2p  : B[k0+2m][col], B[k0+2m+1][col], B[k0+2m+8][col], B[k0+2m+9][col]
//   halves 4..7 = tile 2p+1: same rows, col+8       (m=lane&3, c=lane>>2, col=w*64+16p+c)
// ---------------------------------------------------------------------------
__device__ __align__(16) __half g_wb1[(Ff + Hh) * G4];   // layer 1 (K=272)
__device__ __align__(16) __half g_wb2[2 * Hh * G4];      // layer 2 (K=512)
__device__ float g_b1[G4];
__device__ float g_b2[G4];

__device__ __forceinline__ float sigf(float x) { return 1.0f / (1.0f + __expf(-x)); }

__device__ __forceinline__ unsigned s2u(const void* p) {
    unsigned a;
    asm("{ .reg .u64 t; cvta.to.shared.u64 t, %1; cvt.u32.u64 %0, t; }" : "=r"(a) : "l"(p));
    return a;
}
__device__ __forceinline__ void ldsm4(unsigned& a0, unsigned& a1, unsigned& a2, unsigned& a3,
                                      unsigned addr) {
    asm volatile("ldmatrix.sync.aligned.m8n8.x4.shared.b16 {%0,%1,%2,%3}, [%4];"
                 : "=r"(a0), "=r"(a1), "=r"(a2), "=r"(a3) : "r"(addr));
}
__device__ __forceinline__ void mma16816(float& d0, float& d1, float& d2, float& d3,
                                         unsigned a0, unsigned a1, unsigned a2, unsigned a3,
                                         unsigned b0, unsigned b1) {
    asm volatile("mma.sync.aligned.m16n8k16.row.col.f32.f16.f16.f32 "
                 "{%0,%1,%2,%3}, {%4,%5,%6,%7}, {%8,%9}, {%0,%1,%2,%3};"
                 : "+f"(d0), "+f"(d1), "+f"(d2), "+f"(d3)
                 : "r"(a0), "r"(a1), "r"(a2), "r"(a3), "r"(b0), "r"(b1));
}

// ---------------------------------------------------------------------------
// Prep: pack B fragments + fuse biases.
// ---------------------------------------------------------------------------
__global__ void prep_kernel(const float* __restrict__ wih1, const float* __restrict__ whh1,
                            const float* __restrict__ bih1, const float* __restrict__ bhh1,
                            const float* __restrict__ wih2, const float* __restrict__ whh2,
                            const float* __restrict__ bih2, const float* __restrict__ bhh2) {
    int idx = blockIdx.x * blockDim.x + threadIdx.x;   // over K2T*16*4*32 = 65536
    int t = idx & 31, p = (idx >> 5) & 3, w = (idx >> 7) & 15, kt = idx >> 11;
    int m = t & 3, c = t >> 2;
    int k0 = kt * 16;
    int colA = w * 64 + p * 16 + c;
    int colB = colA + 8;
    int ks[4] = {k0 + 2 * m, k0 + 2 * m + 1, k0 + 2 * m + 8, k0 + 2 * m + 9};

    if (kt < K2T) {   // layer 2: K = 512 (h1 rows 0..255, h2 rows 256..511)
        __align__(16) __half h[8];
        #pragma unroll
        for (int j = 0; j < 4; ++j) {
            int k = ks[j];
            float vA = (k < Hh) ? wih2[colA * Hh + k] : whh2[colA * Hh + (k - Hh)];
            float vB = (k < Hh) ? wih2[colB * Hh + k] : whh2[colB * Hh + (k - Hh)];
            h[j]     = __float2half_rn(vA);
            h[4 + j] = __float2half_rn(vB);
        }
        *((uint4*)g_wb2 + idx) = *(const uint4*)h;
    }
    if (kt < K1T) {   // layer 1: K = 272 (x rows 0..15, h1 rows 16..271)
        __align__(16) __half h[8];
        #pragma unroll
        for (int j = 0; j < 4; ++j) {
            int k = ks[j];
            float vA = (k < Ff) ? wih1[colA * Ff + k] : whh1[colA * Hh + (k - Ff)];
            float vB = (k < Ff) ? wih1[colB * Ff + k] : whh1[colB * Hh + (k - Ff)];
            h[j]     = __float2half_rn(vA);
            h[4 + j] = __float2half_rn(vB);
        }
        *((uint4*)g_wb1 + idx) = *(const uint4*)h;
    }
    if (idx < G4) {
        g_b1[idx] = bih1[idx] + bhh1[idx];
        g_b2[idx] = bih2[idx] + bhh2[idx];
    }
}

// ---------------------------------------------------------------------------
// Fused 2-layer LSTM, tensor-core gates. 1 CTA = 16 batch rows.
// Gate phase: warp w -> 64 gate cols, M=16 batch, mma.m16n8k16, fp32 acc in zs.
// Update phase: thread (u = tid&255, bs = tid>>8) -> unit u, batch rows 8bs..8bs+7.
// ---------------------------------------------------------------------------
__global__ void __launch_bounds__(NT, 1)
lstm_kernel(const float* __restrict__ x,
            const float* __restrict__ wlin, const float* __restrict__ blin,
            float* __restrict__ out) {
    extern __shared__ __align__(16) char smem[];
    __half* hbuf = (__half*)smem;                       // [16][280]
    __half* h12  = hbuf + MB * HST;                     // [16][520]
    float*  zs   = (float*)(h12 + MB * H2ST);           // [16][1032]

    const int tid  = threadIdx.x;
    const int lane = tid & 31;
    const int w    = tid >> 5;
    const int m    = lane & 3;      // threadID_in_group
    const int g    = lane >> 2;     // groupID (row)
    const int b0   = blockIdx.x * MB;

    // ldmatrix lane addressing for A (x4: m0=r0-7/k0-7, m1=r8-15/k0-7, m2=r0-7/k8-15, m3=r8-15/k8-15)
    const int lr  = (lane & 7) + 8 * ((lane >> 3) & 1);
    const int lc8 = (lane >> 4) * 8;
    const unsigned aAddr1 = s2u(hbuf) + (unsigned)(lr * HST + lc8) * 2u;
    const unsigned aAddr2 = s2u(h12)  + (unsigned)(lr * H2ST + lc8) * 2u;

    // zero h state (and x region; x rewritten each step)
    for (int i = tid; i < MB * HST; i += NT)  hbuf[i] = __float2half_rn(0.f);
    for (int i = tid; i < MB * H2ST; i += NT) h12[i]  = __float2half_rn(0.f);

    float c1s[8], c2s[8];
    #pragma unroll
    for (int j = 0; j < 8; ++j) { c1s[j] = 0.f; c2s[j] = 0.f; }

    const uint4* wb1 = (const uint4*)g_wb1 + w * 128 + lane;   // + kt*2048 + p*32
    const uint4* wb2 = (const uint4*)g_wb2 + w * 128 + lane;

    const int uu = tid & 255;    // update-phase unit
    const int bs = tid >> 8;     // update-phase batch half

    __syncthreads();

    for (int t = 0; t < Tt; ++t) {
        // ---- stage x_t (fp16) into hbuf cols 0..15 ----
        if (tid < MB * Ff) {
            int b = tid >> 4, f = tid & 15;
            hbuf[b * HST + f] =
                __float2half_rn(__ldg(&x[((size_t)(b0 + b) * Tt + t) * Ff + f]));
        }
        __syncthreads();

        // ================= LAYER 1 gates (tensor cores) =================
        {
            float acc[8][4];
            #pragma unroll
            for (int nt = 0; nt < 8; ++nt) {
                float2 bv = __ldg((const float2*)&g_b1[w * 64 + nt * 8 + 2 * m]);
                acc[nt][0] = bv.x; acc[nt][1] = bv.y; acc[nt][2] = bv.x; acc[nt][3] = bv.y;
            }
            for (int kt = 0; kt < K1T; ++kt) {
                uint4 bv0 = __ldg(wb1 + kt * 2048);
                uint4 bv1 = __ldg(wb1 + kt * 2048 + 32);
                uint4 bv2 = __ldg(wb1 + kt * 2048 + 64);
                uint4 bv3 = __ldg(wb1 + kt * 2048 + 96);
                unsigned a0, a1, a2, a3;
                ldsm4(a0, a1, a2, a3, aAddr1 + kt * 32);
                mma16816(acc[0][0], acc[0][1], acc[0][2], acc[0][3], a0, a1, a2, a3, bv0.x, bv0.y);
                mma16816(acc[1][0], acc[1][1], acc[1][2], acc[1][3], a0, a1, a2, a3, bv0.z, bv0.w);
                mma16816(acc[2][0], acc[2][1], acc[2][2], acc[2][3], a0, a1, a2, a3, bv1.x, bv1.y);
                mma16816(acc[3][0], acc[3][1], acc[3][2], acc[3][3], a0, a1, a2, a3, bv1.z, bv1.w);
                mma16816(acc[4][0], acc[4][1], acc[4][2], acc[4][3], a0, a1, a2, a3, bv2.x, bv2.y);
                mma16816(acc[5][0], acc[5][1], acc[5][2], acc[5][3], a0, a1, a2, a3, bv2.z, bv2.w);
                mma16816(acc[6][0], acc[6][1], acc[6][2], acc[6][3], a0, a1, a2, a3, bv3.x, bv3.y);
                mma16816(acc[7][0], acc[7][1], acc[7][2], acc[7][3], a0, a1, a2, a3, bv3.z, bv3.w);
            }
            const int cb = w * 64 + 2 * m;
            #pragma unroll
            for (int nt = 0; nt < 8; ++nt) {
                *(float2*)&zs[g * ZST + cb + nt * 8]       = make_float2(acc[nt][0], acc[nt][1]);
                *(float2*)&zs[(g + 8) * ZST + cb + nt * 8] = make_float2(acc[nt][2], acc[nt][3]);
            }
        }
        __syncthreads();

        // ================= LAYER 1 update =================
        {
            #pragma unroll
            for (int j = 0; j < 8; ++j) {
                const int b = bs * 8 + j;
                const float* zp = zs + b * ZST + uu;
                float zi = zp[0], zf = zp[Hh], zg = zp[2 * Hh], zo = zp[3 * Hh];
                c1s[j] = sigf(zf) * c1s[j] + sigf(zi) * tanhf(zg);
                float h = sigf(zo) * tanhf(c1s[j]);
                __half hh = __float2half_rn(h);
                hbuf[b * HST + Ff + uu] = hh;
                h12[b * H2ST + uu]      = hh;
            }
        }
        __syncthreads();

        // ================= LAYER 2 gates (tensor cores) =================
        {
            float acc[8][4];
            #pragma unroll
            for (int nt = 0; nt < 8; ++nt) {
                float2 bv = __ldg((const float2*)&g_b2[w * 64 + nt * 8 + 2 * m]);
                acc[nt][0] = bv.x; acc[nt][1] = bv.y; acc[nt][2] = bv.x; acc[nt][3] = bv.y;
            }
            for (int kt = 0; kt < K2T; ++kt) {
                uint4 bv0 = __ldg(wb2 + kt * 2048);
                uint4 bv1 = __ldg(wb2 + kt * 2048 + 32);
                uint4 bv2 = __ldg(wb2 + kt * 2048 + 64);
                uint4 bv3 = __ldg(wb2 + kt * 2048 + 96);
                unsigned a0, a1, a2, a3;
                ldsm4(a0, a1, a2, a3, aAddr2 + kt * 32);
                mma16816(acc[0][0], acc[0][1], acc[0][2], acc[0][3], a0, a1, a2, a3, bv0.x, bv0.y);
                mma16816(acc[1][0], acc[1][1], acc[1][2], acc[1][3], a0, a1, a2, a3, bv0.z, bv0.w);
                mma16816(acc[2][0], acc[2][1], acc[2][2], acc[2][3], a0, a1, a2, a3, bv1.x, bv1.y);
                mma16816(acc[3][0], acc[3][1], acc[3][2], acc[3][3], a0, a1, a2, a3, bv1.z, bv1.w);
                mma16816(acc[4][0], acc[4][1], acc[4][2], acc[4][3], a0, a1, a2, a3, bv2.x, bv2.y);
                mma16816(acc[5][0], acc[5][1], acc[5][2], acc[5][3], a0, a1, a2, a3, bv2.z, bv2.w);
                mma16816(acc[6][0], acc[6][1], acc[6][2], acc[6][3], a0, a1, a2, a3, bv3.x, bv3.y);
                mma16816(acc[7][0], acc[7][1], acc[7][2], acc[7][3], a0, a1, a2, a3, bv3.z, bv3.w);
            }
            const int cb = w * 64 + 2 * m;
            #pragma unroll
            for (int nt = 0; nt < 8; ++nt) {
                *(float2*)&zs[g * ZST + cb + nt * 8]       = make_float2(acc[nt][0], acc[nt][1]);
                *(float2*)&zs[(g + 8) * ZST + cb + nt * 8] = make_float2(acc[nt][2], acc[nt][3]);
            }
        }
        __syncthreads();

        // ================= LAYER 2 update =================
        {
            #pragma unroll
            for (int j = 0; j < 8; ++j) {
                const int b = bs * 8 + j;
                const float* zp = zs + b * ZST + uu;
                float zi = zp[0], zf = zp[Hh], zg = zp[2 * Hh], zo = zp[3 * Hh];
                c2s[j] = sigf(zf) * c2s[j] + sigf(zi) * tanhf(zg);
                float h = sigf(zo) * tanhf(c2s[j]);
                h12[b * H2ST + Hh + uu] = __float2half_rn(h);
            }
        }
        __syncthreads();
    }

    // ================= linear head: warp w -> batch row w =================
    {
        float s = 0.f;
        #pragma unroll
        for (int u = lane; u < Hh; u += 32)
            s += __half2float(h12[w * H2ST + Hh + u]) * __ldg(&wlin[u]);
        #pragma unroll
        for (int off = 16; off; off >>= 1) s += __shfl_xor_sync(0xffffffffu, s, off);
        if (lane == 0) out[b0 + w] = s + blin[0];
    }
}

// ---------------------------------------------------------------------------
extern "C" void kernel_launch(void* const* d_in, const int* in_sizes, int n_in,
                              void* d_out, int out_size) {
    const float* x    = (const float*)d_in[0];
    const float* wih1 = (const float*)d_in[1];
    const float* whh1 = (const float*)d_in[2];
    const float* bih1 = (const float*)d_in[3];
    const float* bhh1 = (const float*)d_in[4];
    const float* wih2 = (const float*)d_in[5];
    const float* whh2 = (const float*)d_in[6];
    const float* bih2 = (const float*)d_in[7];
    const float* bhh2 = (const float*)d_in[8];
    const float* wlin = (const float*)d_in[9];
    const float* blin = (const float*)d_in[10];
    float* out = (float*)d_out;

    static int smem_set = 0;
    if (!smem_set) {
        cudaFuncSetAttribute(lstm_kernel,
                             cudaFuncAttributeMaxDynamicSharedMemorySize, SMEM_BYTES);
        smem_set = 1;
    }

    prep_kernel<<<(K2T * 16 * 4 * 32 + 255) / 256, 256>>>(wih1, whh1, bih1, bhh1,
                                                          wih2, whh2, bih2, bhh2);
    lstm_kernel<<<NCg, NT, SMEM_BYTES>>>(x, wlin, blin, out);
}